// round 3
// baseline (speedup 1.0000x reference)
#include <cuda_runtime.h>

#define NPTS  4096
#define NPQ   1024
#define NSAMP 32
#define NB    8
#define PXT   262144          /* NB*NPQ*NSAMP */
#define CF    64
#define C0    67
#define M0    64
#define M1    128
#define M2    256
#define EPSB  1e-5f
#define OUT_XYZ 24576         /* NB*NPQ*3 */

/* scratch activations (bss, no runtime alloc) */
__device__ float g_y0[(size_t)M0 * PXT];   /* 64 MB  */
__device__ float g_y1[(size_t)M1 * PXT];   /* 128 MB */

/* pre-transposed weights [k][co] */
__device__ float g_Wt0[C0 * M0];
__device__ float g_Wt1[64 * M1];
__device__ float g_Wt2[M1 * M2];

/* per-channel stats, packed: layer0 @0 (64), layer1 @64 (128), layer2 @192 (256) */
__device__ float g_sum[448];
__device__ float g_sq[448];
__device__ float g_aa[448];
__device__ float g_cc[448];

extern __shared__ float sm[];

/* zero stats + transpose all weights into [k][co] layout (stays hot in L2) */
__global__ void k_prep(const float* __restrict__ W0,
                       const float* __restrict__ W1,
                       const float* __restrict__ W2) {
    int t = blockIdx.x * blockDim.x + threadIdx.x;
    int nth = gridDim.x * blockDim.x;
    if (t < 448) { g_sum[t] = 0.f; g_sq[t] = 0.f; }
    for (int e = t; e < C0 * M0; e += nth) {
        int k = e / M0, co = e % M0;
        g_Wt0[e] = W0[co * C0 + k];
    }
    for (int e = t; e < 64 * M1; e += nth) {
        int k = e >> 7, co = e & 127;
        g_Wt1[e] = W1[co * 64 + k];
    }
    for (int e = t; e < M1 * M2; e += nth) {
        int k = e >> 8, co = e & 255;
        g_Wt2[e] = W2[co * M1 + k];
    }
}

__global__ void k_fold(const float* __restrict__ gamma,
                       const float* __restrict__ beta, int off, int C) {
    int i = blockIdx.x * blockDim.x + threadIdx.x;
    if (i < C) {
        const float inv = 1.0f / (float)PXT;
        float mu  = g_sum[off + i] * inv;
        float var = g_sq[off + i] * inv - mu * mu;
        float r   = rsqrtf(var + EPSB);
        float a   = gamma[i] * r;
        g_aa[off + i] = a;
        g_cc[off + i] = beta[i] - a * mu;
    }
}

/* -------- layer 0: gather + GEMM(64 x PX x 67) + stats0 -------- */
__global__ __launch_bounds__(256) void k_gemm0(
    const float* __restrict__ xyz, const float* __restrict__ pts,
    const int* __restrict__ smp, const int* __restrict__ nbr)
{
    float* Ws = sm;                       /* [k][co]  C0*M0  */
    float* Xs = sm + C0 * M0;             /* [k][px]  C0*128 */
    int*   s_nidx = (int*)(sm + C0 * M0 + C0 * 128);

    int tid = threadIdx.x;
    int px0 = blockIdx.x * 128;
    int b   = px0 >> 15;                  /* 128-px tile never crosses a batch */

    /* straight copy, coalesced + conflict-free (already [k][co]) */
    for (int e = tid; e < (C0 * M0) / 4; e += 256)
        ((float4*)Ws)[e] = ((const float4*)g_Wt0)[e];

    if (tid < 128) {
        int pxg = px0 + tid;
        int ni  = nbr[pxg];
        s_nidx[tid] = ni;
        int si  = smp[pxg >> 5];
        const float* xn = xyz + (size_t)(b * NPTS + ni) * 3;
        const float* xc = xyz + (size_t)(b * NPTS + si) * 3;
        Xs[0 * 128 + tid] = xn[0] - xc[0];
        Xs[1 * 128 + tid] = xn[1] - xc[1];
        Xs[2 * 128 + tid] = xn[2] - xc[2];
    }
    __syncthreads();
    for (int e = tid; e < CF * 128; e += 256) {
        int k = e >> 7, px = e & 127;
        Xs[(3 + k) * 128 + px] = pts[(b * CF + k) * NPTS + s_nidx[px]];
    }
    __syncthreads();

    int tc = tid & 15, tp = tid >> 4;     /* co = tc*4.., px = tp*8.. */
    float acc[4][8];
#pragma unroll
    for (int i = 0; i < 4; i++)
#pragma unroll
        for (int j = 0; j < 8; j++) acc[i][j] = 0.f;

#pragma unroll 2
    for (int k = 0; k < C0; k++) {
        const float4 a  = *(const float4*)(Ws + k * M0 + tc * 4);
        const float4 x0 = *(const float4*)(Xs + k * 128 + tp * 8);
        const float4 x1 = *(const float4*)(Xs + k * 128 + tp * 8 + 4);
        float av[4] = {a.x, a.y, a.z, a.w};
        float xv[8] = {x0.x, x0.y, x0.z, x0.w, x1.x, x1.y, x1.z, x1.w};
#pragma unroll
        for (int i = 0; i < 4; i++)
#pragma unroll
            for (int j = 0; j < 8; j++) acc[i][j] = fmaf(av[i], xv[j], acc[i][j]);
    }

    float ps[4], pq[4];
#pragma unroll
    for (int i = 0; i < 4; i++) {
        int co = tc * 4 + i;
        float s = 0.f, q = 0.f;
#pragma unroll
        for (int j = 0; j < 8; j++) { float v = acc[i][j]; s += v; q += v * v; }
        float* dst = g_y0 + (size_t)co * PXT + px0 + tp * 8;
        *(float4*)dst       = make_float4(acc[i][0], acc[i][1], acc[i][2], acc[i][3]);
        *(float4*)(dst + 4) = make_float4(acc[i][4], acc[i][5], acc[i][6], acc[i][7]);
        ps[i] = s; pq[i] = q;
    }
#pragma unroll
    for (int i = 0; i < 4; i++) {
        ps[i] += __shfl_xor_sync(0xffffffffu, ps[i], 16);
        pq[i] += __shfl_xor_sync(0xffffffffu, pq[i], 16);
    }
    if (!(tid & 16)) {
#pragma unroll
        for (int i = 0; i < 4; i++) {
            atomicAdd(&g_sum[tc * 4 + i], ps[i]);
            atomicAdd(&g_sq[tc * 4 + i], pq[i]);
        }
    }
}

/* -------- layer 1: BN0+ReLU fused load, GEMM(128 x PX x 64) + stats1
   split register tiles: co in {tc*4..+3, 64+tc*4..+3}, px in {tp*4..+3, 64+tp*4..+3}
   -> all LDS.128 conflict-free -------- */
__global__ __launch_bounds__(256) void k_gemm1()
{
    float* Ws  = sm;                 /* [k][co] 64*128 */
    float* Xs  = sm + 64 * M1;       /* [k][px] 64*128 */
    float* s_a = sm + 2 * 64 * M1;   /* 64 */
    float* s_c = s_a + 64;

    int tid = threadIdx.x;
    int px0 = blockIdx.x * 128;

    if (tid < 64) { s_a[tid] = g_aa[tid]; s_c[tid] = g_cc[tid]; }
    for (int e = tid; e < (64 * M1) / 4; e += 256)
        ((float4*)Ws)[e] = ((const float4*)g_Wt1)[e];
    __syncthreads();
    for (int e = tid; e < 64 * 128; e += 256) {
        int k = e >> 7, px = e & 127;
        float v = g_y0[(size_t)k * PXT + px0 + px];
        Xs[k * 128 + px] = fmaxf(fmaf(s_a[k], v, s_c[k]), 0.f);
    }
    __syncthreads();

    int tc = tid & 15, tp = tid >> 4;
    float acc[8][8];
#pragma unroll
    for (int i = 0; i < 8; i++)
#pragma unroll
        for (int j = 0; j < 8; j++) acc[i][j] = 0.f;

#pragma unroll 2
    for (int k = 0; k < 64; k++) {
        const float4 a0 = *(const float4*)(Ws + k * M1 + tc * 4);
        const float4 a1 = *(const float4*)(Ws + k * M1 + 64 + tc * 4);
        const float4 b0 = *(const float4*)(Xs + k * 128 + tp * 4);
        const float4 b1 = *(const float4*)(Xs + k * 128 + 64 + tp * 4);
        float av[8] = {a0.x, a0.y, a0.z, a0.w, a1.x, a1.y, a1.z, a1.w};
        float bv[8] = {b0.x, b0.y, b0.z, b0.w, b1.x, b1.y, b1.z, b1.w};
#pragma unroll
        for (int i = 0; i < 8; i++)
#pragma unroll
            for (int j = 0; j < 8; j++) acc[i][j] = fmaf(av[i], bv[j], acc[i][j]);
    }

    float ps[8], pq[8];
#pragma unroll
    for (int i = 0; i < 8; i++) {
        int co = (i < 4) ? (tc * 4 + i) : (64 + tc * 4 + i - 4);
        float s = 0.f, q = 0.f;
#pragma unroll
        for (int j = 0; j < 8; j++) { float v = acc[i][j]; s += v; q += v * v; }
        float* dst = g_y1 + (size_t)co * PXT + px0;
        *(float4*)(dst + tp * 4)      = make_float4(acc[i][0], acc[i][1], acc[i][2], acc[i][3]);
        *(float4*)(dst + 64 + tp * 4) = make_float4(acc[i][4], acc[i][5], acc[i][6], acc[i][7]);
        ps[i] = s; pq[i] = q;
    }
#pragma unroll
    for (int i = 0; i < 8; i++) {
        ps[i] += __shfl_xor_sync(0xffffffffu, ps[i], 16);
        pq[i] += __shfl_xor_sync(0xffffffffu, pq[i], 16);
    }
    if (!(tid & 16)) {
#pragma unroll
        for (int i = 0; i < 8; i++) {
            int co = (i < 4) ? (tc * 4 + i) : (64 + tc * 4 + i - 4);
            atomicAdd(&g_sum[64 + co], ps[i]);
            atomicAdd(&g_sq[64 + co], pq[i]);
        }
    }
}

/* -------- layer 2: BN1+ReLU fused load, GEMM(256 x PX x 128) + stats2
           + max over NS (BN2+ReLU monotone => commute), write raw max -------- */
__global__ __launch_bounds__(256) void k_gemm2(float* __restrict__ out)
{
    float* Ws     = sm;              /* [k][co_local] 64*128 per K-chunk */
    float* Xs     = sm + 8192;       /* [k][px] 64*128 */
    float* s_a    = sm + 16384;      /* 128 */
    float* s_c    = s_a + 128;
    float* s_pmax = s_c + 128;       /* 32 rows x 128 co, row r = px r*4..r*4+3 */

    int tid = threadIdx.x;
    int px0 = blockIdx.x * 128;
    int co0 = blockIdx.y * 128;

    if (tid < 128) { s_a[tid] = g_aa[64 + tid]; s_c[tid] = g_cc[64 + tid]; }

    int tc = tid & 15, tp = tid >> 4;
    float acc[8][8];
#pragma unroll
    for (int i = 0; i < 8; i++)
#pragma unroll
        for (int j = 0; j < 8; j++) acc[i][j] = 0.f;

    for (int kc = 0; kc < 2; kc++) {
        int kb = kc << 6;
        __syncthreads();    /* s_a ready (kc=0) / smem reuse safe (kc=1) */
        /* Wt2 is [k 0..127][co 0..255]; copy rows kb..kb+63, cols co0..co0+127 */
        for (int e = tid; e < 2048; e += 256) {
            int k = e >> 5, cq = e & 31;
            ((float4*)Ws)[k * 32 + cq] =
                ((const float4*)g_Wt2)[(size_t)(kb + k) * 64 + (co0 >> 2) + cq];
        }
        for (int e = tid; e < 64 * 128; e += 256) {
            int k = e >> 7, px = e & 127;
            float v = g_y1[(size_t)(kb + k) * PXT + px0 + px];
            Xs[k * 128 + px] = fmaxf(fmaf(s_a[kb + k], v, s_c[kb + k]), 0.f);
        }
        __syncthreads();
#pragma unroll 2
        for (int k = 0; k < 64; k++) {
            const float4 a0 = *(const float4*)(Ws + k * M1 + tc * 4);
            const float4 a1 = *(const float4*)(Ws + k * M1 + 64 + tc * 4);
            const float4 b0 = *(const float4*)(Xs + k * 128 + tp * 4);
            const float4 b1 = *(const float4*)(Xs + k * 128 + 64 + tp * 4);
            float av[8] = {a0.x, a0.y, a0.z, a0.w, a1.x, a1.y, a1.z, a1.w};
            float bv[8] = {b0.x, b0.y, b0.z, b0.w, b1.x, b1.y, b1.z, b1.w};
#pragma unroll
            for (int i = 0; i < 8; i++)
#pragma unroll
                for (int j = 0; j < 8; j++) acc[i][j] = fmaf(av[i], bv[j], acc[i][j]);
        }
    }

    float ps[8], pq[8], pml[8], pmh[8];
#pragma unroll
    for (int i = 0; i < 8; i++) {
        float s = 0.f, q = 0.f, ml = -3.4e38f, mh = -3.4e38f;
#pragma unroll
        for (int j = 0; j < 4; j++) {
            float v = acc[i][j];
            s += v; q += v * v; ml = fmaxf(ml, v);
        }
#pragma unroll
        for (int j = 4; j < 8; j++) {
            float v = acc[i][j];
            s += v; q += v * v; mh = fmaxf(mh, v);
        }
        ps[i] = s; pq[i] = q; pml[i] = ml; pmh[i] = mh;
    }
#pragma unroll
    for (int i = 0; i < 8; i++) {
        ps[i] += __shfl_xor_sync(0xffffffffu, ps[i], 16);
        pq[i] += __shfl_xor_sync(0xffffffffu, pq[i], 16);
    }
    if (!(tid & 16)) {
#pragma unroll
        for (int i = 0; i < 8; i++) {
            int co = (i < 4) ? (tc * 4 + i) : (64 + tc * 4 + i - 4);
            atomicAdd(&g_sum[192 + co0 + co], ps[i]);
            atomicAdd(&g_sq[192 + co0 + co], pq[i]);
        }
    }
#pragma unroll
    for (int i = 0; i < 8; i++) {
        int co = (i < 4) ? (tc * 4 + i) : (64 + tc * 4 + i - 4);
        s_pmax[tp * 128 + co]        = pml[i];   /* px tp*4..+3      -> row tp    */
        s_pmax[(16 + tp) * 128 + co] = pmh[i];   /* px 64+tp*4..+3   -> row 16+tp */
    }
    __syncthreads();

    /* 4 np-groups (32 px each = rows 8g..8g+7) x 128 co per tile */
    for (int e = tid; e < 512; e += 256) {
        int g = e >> 7, co = e & 127;
        float v = -3.4e38f;
#pragma unroll
        for (int r = 0; r < 8; r++)
            v = fmaxf(v, s_pmax[(8 * g + r) * 128 + co]);
        int npf = (px0 >> 5) + g;              /* = b*NPQ + np */
        int b = npf >> 10, np = npf & 1023;
        out[OUT_XYZ + ((b * M2 + co0 + co) * NPQ + np)] = v;
    }
}

/* in-place BN2 + ReLU on the maxed output */
__global__ void k_final(float* __restrict__ out) {
    int i = blockIdx.x * 256 + threadIdx.x;
    if (i < NB * M2 * NPQ) {
        int co = (i >> 10) & 255;
        float v = out[OUT_XYZ + i];
        out[OUT_XYZ + i] = fmaxf(fmaf(g_aa[192 + co], v, g_cc[192 + co]), 0.f);
    }
}

__global__ void k_xyz(const float* __restrict__ xyz, const int* __restrict__ smp,
                      float* __restrict__ out) {
    int i = blockIdx.x * 256 + threadIdx.x;
    if (i < NB * NPQ) {
        int b = i >> 10;
        int si = smp[i];
        const float* s = xyz + (size_t)(b * NPTS + si) * 3;
        out[i * 3 + 0] = s[0];
        out[i * 3 + 1] = s[1];
        out[i * 3 + 2] = s[2];
    }
}

extern "C" void kernel_launch(void* const* d_in, const int* in_sizes, int n_in,
                              void* d_out, int out_size) {
    const float* xyz = (const float*)d_in[0];
    const float* pts = (const float*)d_in[1];
    const int*   smp = (const int*)d_in[2];
    const int*   nbr = (const int*)d_in[3];
    const float* W0  = (const float*)d_in[4];
    const float* g0  = (const float*)d_in[6];
    const float* be0 = (const float*)d_in[7];
    const float* W1  = (const float*)d_in[8];
    const float* g1  = (const float*)d_in[10];
    const float* be1 = (const float*)d_in[11];
    const float* W2  = (const float*)d_in[12];
    const float* g2  = (const float*)d_in[14];
    const float* be2 = (const float*)d_in[15];
    float* out = (float*)d_out;

    const int SM0 = (C0 * M0 + C0 * 128 + 128) * 4;       /* 51968 B */
    const int SM1 = (64 * M1 * 2 + 128) * 4;              /* 66048 B */
    const int SM2 = (64 * M1 * 2 + 256 + 32 * 128) * 4;   /* 82944 B */
    cudaFuncSetAttribute(k_gemm0, cudaFuncAttributeMaxDynamicSharedMemorySize, SM0);
    cudaFuncSetAttribute(k_gemm1, cudaFuncAttributeMaxDynamicSharedMemorySize, SM1);
    cudaFuncSetAttribute(k_gemm2, cudaFuncAttributeMaxDynamicSharedMemorySize, SM2);

    k_prep<<<64, 256>>>(W0, W1, W2);
    k_gemm0<<<PXT / 128, 256, SM0>>>(xyz, pts, smp, nbr);
    k_fold<<<1, 64>>>(g0, be0, 0, 64);
    k_gemm1<<<PXT / 128, 256, SM1>>>();
    k_fold<<<1, 128>>>(g1, be1, 64, 128);
    k_gemm2<<<dim3(PXT / 128, 2), 256, SM2>>>(out);
    k_fold<<<1, 256>>>(g2, be2, 192, 256);
    k_final<<<(NB * M2 * NPQ + 255) / 256, 256>>>(out);
    k_xyz<<<(NB * NPQ + 255) / 256, 256>>>(xyz, smp, out);
}

// round 5
// speedup vs baseline: 2.6576x; 2.6576x over previous
#include <cuda_runtime.h>

#define NPTS  4096
#define NPQ   1024
#define NB    8
#define PXT   262144
#define EPSB  1e-5f
#define OUT_XYZ 24576
#define FLT_BIG 3.4e38f

typedef unsigned int   u32;
typedef unsigned short u16;

/* packed bf16 hi|lo activations, px-major */
__device__ u32 g_y0u[(size_t)PXT * 64];    /* [px][64]  64 MB  */
__device__ u32 g_y1u[(size_t)PXT * 128];   /* [px][128] 128 MB */

/* pre-split weights, [co][k] bf16 bits */
__device__ u16 g_W0h[64 * 80],  g_W0l[64 * 80];     /* padded k=80 */
__device__ u16 g_W1h[128 * 64], g_W1l[128 * 64];
__device__ u16 g_W2h[256 * 128], g_W2l[256 * 128];

__device__ float g_sum[448], g_sq[448], g_aa[448], g_cc[448];

/* ---------- helpers ---------- */
__device__ __forceinline__ u32 bf16bits(float v) {
    u32 u = __float_as_uint(v);
    return (u + 0x7fffu + ((u >> 16) & 1u)) >> 16;
}
__device__ __forceinline__ void split2(float v, u32& hb, u32& lb) {
    hb = bf16bits(v);
    lb = bf16bits(v - __uint_as_float(hb << 16));
}
__device__ __forceinline__ u32 packhl(float v) {
    u32 hb, lb; split2(v, hb, lb);
    return (hb << 16) | lb;
}
__device__ __forceinline__ float unpk(u32 p) {
    return __uint_as_float(p & 0xffff0000u) + __uint_as_float((p & 0xffffu) << 16);
}
__device__ __forceinline__ u32 smem_u32_of(const void* p) {
    u32 a;
    asm("{ .reg .u64 t; cvta.to.shared.u64 t, %1; cvt.u32.u64 %0, t; }" : "=r"(a) : "l"(p));
    return a;
}
__device__ __forceinline__ void ldsm4(u32* r, u32 addr) {
    asm volatile("ldmatrix.sync.aligned.m8n8.x4.shared.b16 {%0,%1,%2,%3}, [%4];"
        : "=r"(r[0]), "=r"(r[1]), "=r"(r[2]), "=r"(r[3]) : "r"(addr));
}
__device__ __forceinline__ void hmma(float* d, const u32* a, u32 b0, u32 b1) {
    asm volatile("mma.sync.aligned.m16n8k16.row.col.f32.bf16.bf16.f32 "
        "{%0,%1,%2,%3}, {%4,%5,%6,%7}, {%8,%9}, {%0,%1,%2,%3};"
        : "+f"(d[0]), "+f"(d[1]), "+f"(d[2]), "+f"(d[3])
        : "r"(a[0]), "r"(a[1]), "r"(a[2]), "r"(a[3]), "r"(b0), "r"(b1));
}

extern __shared__ char smc[];

/* ---------- prep: stats zero + weight split images ---------- */
__global__ void k_prep(const float* __restrict__ W0, const float* __restrict__ W1,
                       const float* __restrict__ W2) {
    int t0 = blockIdx.x * blockDim.x + threadIdx.x;
    int nth = gridDim.x * blockDim.x;
    for (int t = t0; t < 448; t += nth) { g_sum[t] = 0.f; g_sq[t] = 0.f; }
    for (int e = t0; e < 64 * 80; e += nth) {
        int co = e / 80, k = e - co * 80;
        float v = (k < 67) ? W0[co * 67 + k] : 0.f;
        u32 hb, lb; split2(v, hb, lb);
        g_W0h[e] = (u16)hb; g_W0l[e] = (u16)lb;
    }
    for (int e = t0; e < 128 * 64; e += nth) {
        u32 hb, lb; split2(W1[e], hb, lb);
        g_W1h[e] = (u16)hb; g_W1l[e] = (u16)lb;
    }
    for (int e = t0; e < 256 * 128; e += nth) {
        u32 hb, lb; split2(W2[e], hb, lb);
        g_W2h[e] = (u16)hb; g_W2l[e] = (u16)lb;
    }
}

__global__ void k_fold(const float* __restrict__ gamma, const float* __restrict__ beta,
                       int off, int C) {
    int i = blockIdx.x * blockDim.x + threadIdx.x;
    if (i < C) {
        const float inv = 1.0f / (float)PXT;
        float mu = g_sum[off + i] * inv;
        float var = g_sq[off + i] * inv - mu * mu;
        float a = gamma[i] * rsqrtf(var + EPSB);
        g_aa[off + i] = a;
        g_cc[off + i] = beta[i] - a * mu;
    }
}

/* ================= layer 0: gather + GEMM(px128 x co64 x k80) ================
   pitch 176B (11x16B, odd) -> conflict-free ldmatrix */
__global__ __launch_bounds__(256, 2) void k_g0(
    const float* __restrict__ xyz, const float* __restrict__ pts,
    const int* __restrict__ smp, const int* __restrict__ nbr)
{
    const int XHo = 0, XLo = 22528, WHo = 45056, WLo = 56320;  /* bytes */
    u16* XH = (u16*)(smc + XHo); u16* XL = (u16*)(smc + XLo);
    u16* WH = (u16*)(smc + WHo); u16* WL = (u16*)(smc + WLo);

    int tid = threadIdx.x, wid = tid >> 5, lane = tid & 31;
    int px0 = blockIdx.x * 128, b = px0 >> 15;

    for (int e = tid; e < 5120; e += 256) {
        int row = e / 80, k = e - row * 80;
        WH[row * 88 + k] = g_W0h[e];
        WL[row * 88 + k] = g_W0l[e];
    }
    {
        int r = tid & 127, half = tid >> 7;
        int px = px0 + r;
        int ni = nbr[px];
        const float* prow = pts + (size_t)b * 64 * NPTS + ni;
        if (half == 0) {
            int si = smp[px >> 5];
            const float* xn = xyz + (size_t)(b * NPTS + ni) * 3;
            const float* xc = xyz + (size_t)(b * NPTS + si) * 3;
#pragma unroll
            for (int k = 0; k < 3; k++) {
                u32 hb, lb; split2(xn[k] - xc[k], hb, lb);
                XH[r * 88 + k] = (u16)hb; XL[r * 88 + k] = (u16)lb;
            }
            for (int c = 0; c < 37; c++) {
                u32 hb, lb; split2(prow[(size_t)c * NPTS], hb, lb);
                XH[r * 88 + 3 + c] = (u16)hb; XL[r * 88 + 3 + c] = (u16)lb;
            }
        } else {
            for (int c = 37; c < 64; c++) {
                u32 hb, lb; split2(prow[(size_t)c * NPTS], hb, lb);
                XH[r * 88 + 3 + c] = (u16)hb; XL[r * 88 + 3 + c] = (u16)lb;
            }
            for (int k = 67; k < 80; k++) { XH[r * 88 + k] = 0; XL[r * 88 + k] = 0; }
        }
    }
    __syncthreads();

    int pxg = wid >> 1, cog = wid & 1;
    u32 smb = smem_u32_of(smc);
    /* A address bases */
    u32 arow = (u32)(pxg * 32 + (lane & 15)) * 176 + ((lane >> 4) << 4);
    u32 brow = (u32)(cog * 32 + ((lane >> 4) << 3) + (lane & 7)) * 176 + (((lane >> 3) & 1) << 4);

    float acc[2][4][4];
#pragma unroll
    for (int m = 0; m < 2; m++)
#pragma unroll
        for (int n = 0; n < 4; n++)
#pragma unroll
            for (int i = 0; i < 4; i++) acc[m][n][i] = 0.f;

#pragma unroll
    for (int ks = 0; ks < 5; ks++) {
        u32 ah[2][4], al[2][4], bh[2][4], bl[2][4];
#pragma unroll
        for (int m = 0; m < 2; m++) {
            ldsm4(ah[m], smb + XHo + arow + (u32)m * 16 * 176 + ks * 32);
            ldsm4(al[m], smb + XLo + arow + (u32)m * 16 * 176 + ks * 32);
        }
#pragma unroll
        for (int g = 0; g < 2; g++) {
            ldsm4(bh[g], smb + WHo + brow + (u32)g * 16 * 176 + ks * 32);
            ldsm4(bl[g], smb + WLo + brow + (u32)g * 16 * 176 + ks * 32);
        }
#pragma unroll
        for (int m = 0; m < 2; m++)
#pragma unroll
            for (int n = 0; n < 4; n++) {
                int pr = n >> 1, sb = (n & 1) * 2;
                hmma(acc[m][n], ah[m], bh[pr][sb], bh[pr][sb + 1]);
                hmma(acc[m][n], ah[m], bl[pr][sb], bl[pr][sb + 1]);
                hmma(acc[m][n], al[m], bh[pr][sb], bh[pr][sb + 1]);
            }
    }

#pragma unroll
    for (int m = 0; m < 2; m++)
#pragma unroll
        for (int n = 0; n < 4; n++) {
            int px = px0 + pxg * 32 + m * 16 + (lane >> 2);
            int co = cog * 32 + n * 8 + ((lane & 3) << 1);
            uint2 v0 = { packhl(acc[m][n][0]), packhl(acc[m][n][1]) };
            uint2 v1 = { packhl(acc[m][n][2]), packhl(acc[m][n][3]) };
            *(uint2*)&g_y0u[(size_t)px * 64 + co] = v0;
            *(uint2*)&g_y0u[(size_t)(px + 8) * 64 + co] = v1;
        }
}

/* ---------- stats scans ---------- */
__global__ void k_stats0() {
    __shared__ float ss[64], sq[64];
    int tid = threadIdx.x;
    if (tid < 64) { ss[tid] = 0.f; sq[tid] = 0.f; }
    __syncthreads();
    float s = 0.f, q = 0.f;
    for (size_t e = (size_t)blockIdx.x * 256 + tid; e < (size_t)PXT * 64; e += (size_t)gridDim.x * 256) {
        float x = unpk(g_y0u[e]);
        s += x; q += x * x;
    }
    atomicAdd(&ss[tid & 63], s);
    atomicAdd(&sq[tid & 63], q);
    __syncthreads();
    if (tid < 64) { atomicAdd(&g_sum[tid], ss[tid]); atomicAdd(&g_sq[tid], sq[tid]); }
}
__global__ void k_stats1() {
    __shared__ float ss[128], sq[128];
    int tid = threadIdx.x;
    if (tid < 128) { ss[tid] = 0.f; sq[tid] = 0.f; }
    __syncthreads();
    float s = 0.f, q = 0.f;
    for (size_t e = (size_t)blockIdx.x * 256 + tid; e < (size_t)PXT * 128; e += (size_t)gridDim.x * 256) {
        float x = unpk(g_y1u[e]);
        s += x; q += x * x;
    }
    atomicAdd(&ss[tid & 127], s);
    atomicAdd(&sq[tid & 127], q);
    __syncthreads();
    if (tid < 128) { atomicAdd(&g_sum[64 + tid], ss[tid]); atomicAdd(&g_sq[64 + tid], sq[tid]); }
}

/* ================= layer 1: GEMM(px64 x co128 x k64), BN0+ReLU staged ====== */
__global__ __launch_bounds__(256, 2) void k_g1()
{
    const int XHo = 0, XLo = 9216, WHo = 18432, WLo = 36864;  /* bytes */
    u16* XH = (u16*)(smc + XHo); u16* XL = (u16*)(smc + XLo);
    u16* WH = (u16*)(smc + WHo); u16* WL = (u16*)(smc + WLo);
    float* s_a = (float*)(smc + 55296);
    float* s_c = s_a + 64;

    int tid = threadIdx.x, wid = tid >> 5, lane = tid & 31;
    int px0 = blockIdx.x * 64;

    if (tid < 64) { s_a[tid] = g_aa[tid]; s_c[tid] = g_cc[tid]; }
    for (int e = tid; e < 8192; e += 256) {
        int row = e >> 6, k = e & 63;
        WH[row * 72 + k] = g_W1h[e];
        WL[row * 72 + k] = g_W1l[e];
    }
    __syncthreads();
    {
        int r = tid >> 2, q = tid & 3;
        int px = px0 + r;
#pragma unroll
        for (int j2 = 0; j2 < 4; j2++) {
            uint4 w = *(const uint4*)&g_y0u[(size_t)px * 64 + q * 16 + j2 * 4];
            u32 ww[4] = { w.x, w.y, w.z, w.w };
#pragma unroll
            for (int jj = 0; jj < 4; jj++) {
                int k = q * 16 + j2 * 4 + jj;
                float v = fmaxf(fmaf(s_a[k], unpk(ww[jj]), s_c[k]), 0.f);
                u32 hb, lb; split2(v, hb, lb);
                XH[r * 72 + k] = (u16)hb; XL[r * 72 + k] = (u16)lb;
            }
        }
    }
    __syncthreads();

    int pxg = wid >> 2, cog = wid & 3;
    u32 smb = smem_u32_of(smc);
    u32 arow = (u32)(pxg * 32 + (lane & 15)) * 144 + ((lane >> 4) << 4);
    u32 brow = (u32)(cog * 32 + ((lane >> 4) << 3) + (lane & 7)) * 144 + (((lane >> 3) & 1) << 4);

    float acc[2][4][4];
#pragma unroll
    for (int m = 0; m < 2; m++)
#pragma unroll
        for (int n = 0; n < 4; n++)
#pragma unroll
            for (int i = 0; i < 4; i++) acc[m][n][i] = 0.f;

#pragma unroll
    for (int ks = 0; ks < 4; ks++) {
        u32 ah[2][4], al[2][4], bh[2][4], bl[2][4];
#pragma unroll
        for (int m = 0; m < 2; m++) {
            ldsm4(ah[m], smb + XHo + arow + (u32)m * 16 * 144 + ks * 32);
            ldsm4(al[m], smb + XLo + arow + (u32)m * 16 * 144 + ks * 32);
        }
#pragma unroll
        for (int g = 0; g < 2; g++) {
            ldsm4(bh[g], smb + WHo + brow + (u32)g * 16 * 144 + ks * 32);
            ldsm4(bl[g], smb + WLo + brow + (u32)g * 16 * 144 + ks * 32);
        }
#pragma unroll
        for (int m = 0; m < 2; m++)
#pragma unroll
            for (int n = 0; n < 4; n++) {
                int pr = n >> 1, sb = (n & 1) * 2;
                hmma(acc[m][n], ah[m], bh[pr][sb], bh[pr][sb + 1]);
                hmma(acc[m][n], ah[m], bl[pr][sb], bl[pr][sb + 1]);
                hmma(acc[m][n], al[m], bh[pr][sb], bh[pr][sb + 1]);
            }
    }

#pragma unroll
    for (int m = 0; m < 2; m++)
#pragma unroll
        for (int n = 0; n < 4; n++) {
            int px = px0 + pxg * 32 + m * 16 + (lane >> 2);
            int co = cog * 32 + n * 8 + ((lane & 3) << 1);
            uint2 v0 = { packhl(acc[m][n][0]), packhl(acc[m][n][1]) };
            uint2 v1 = { packhl(acc[m][n][2]), packhl(acc[m][n][3]) };
            *(uint2*)&g_y1u[(size_t)px * 128 + co] = v0;
            *(uint2*)&g_y1u[(size_t)(px + 8) * 128 + co] = v1;
        }
}

/* ====== layer 2: GEMM(px64 x co128 x k128 in 2 chunks) + stats2 + NS-max === */
__global__ __launch_bounds__(256, 2) void k_g2(float* __restrict__ out)
{
    const int XHo = 0, XLo = 9216, WHo = 18432, WLo = 36864;
    u16* XH = (u16*)(smc + XHo); u16* XL = (u16*)(smc + XLo);
    u16* WH = (u16*)(smc + WHo); u16* WL = (u16*)(smc + WLo);
    float* s_a = (float*)(smc + 55296);
    float* s_c = s_a + 128;

    int tid = threadIdx.x, wid = tid >> 5, lane = tid & 31;
    int px0 = blockIdx.x * 64;
    int coB = blockIdx.y * 128;

    if (tid < 128) { s_a[tid] = g_aa[64 + tid]; s_c[tid] = g_cc[64 + tid]; }

    int pxg = wid >> 2, cog = wid & 3;
    u32 smb = smem_u32_of(smc);
    u32 arow = (u32)(pxg * 32 + (lane & 15)) * 144 + ((lane >> 4) << 4);
    u32 brow = (u32)(cog * 32 + ((lane >> 4) << 3) + (lane & 7)) * 144 + (((lane >> 3) & 1) << 4);

    float acc[2][4][4];
#pragma unroll
    for (int m = 0; m < 2; m++)
#pragma unroll
        for (int n = 0; n < 4; n++)
#pragma unroll
            for (int i = 0; i < 4; i++) acc[m][n][i] = 0.f;

    for (int kc = 0; kc < 2; kc++) {
        __syncthreads();
        for (int e = tid; e < 8192; e += 256) {
            int row = e >> 6, k = e & 63;
            WH[row * 72 + k] = g_W2h[(size_t)(coB + row) * 128 + kc * 64 + k];
            WL[row * 72 + k] = g_W2l[(size_t)(coB + row) * 128 + kc * 64 + k];
        }
        {
            int r = tid >> 2, q = tid & 3;
            int px = px0 + r;
#pragma unroll
            for (int j2 = 0; j2 < 4; j2++) {
                int kg = kc * 64 + q * 16 + j2 * 4;
                uint4 w = *(const uint4*)&g_y1u[(size_t)px * 128 + kg];
                u32 ww[4] = { w.x, w.y, w.z, w.w };
#pragma unroll
                for (int jj = 0; jj < 4; jj++) {
                    float v = fmaxf(fmaf(s_a[kg + jj], unpk(ww[jj]), s_c[kg + jj]), 0.f);
                    u32 hb, lb; split2(v, hb, lb);
                    int k = q * 16 + j2 * 4 + jj;
                    XH[r * 72 + k] = (u16)hb; XL[r * 72 + k] = (u16)lb;
                }
            }
        }
        __syncthreads();

#pragma unroll
        for (int ks = 0; ks < 4; ks++) {
            u32 ah[2][4], al[2][4], bh[2][4], bl[2][4];
#pragma unroll
            for (int m = 0; m < 2; m++) {
                ldsm4(ah[m], smb + XHo + arow + (u32)m * 16 * 144 + ks * 32);
                ldsm4(al[m], smb + XLo + arow + (u32)m * 16 * 144 + ks * 32);
            }
#pragma unroll
            for (int g = 0; g < 2; g++) {
                ldsm4(bh[g], smb + WHo + brow + (u32)g * 16 * 144 + ks * 32);
                ldsm4(bl[g], smb + WLo + brow + (u32)g * 16 * 144 + ks * 32);
            }
#pragma unroll
            for (int m = 0; m < 2; m++)
#pragma unroll
                for (int n = 0; n < 4; n++) {
                    int pr = n >> 1, sb = (n & 1) * 2;
                    hmma(acc[m][n], ah[m], bh[pr][sb], bh[pr][sb + 1]);
                    hmma(acc[m][n], ah[m], bl[pr][sb], bl[pr][sb + 1]);
                    hmma(acc[m][n], al[m], bh[pr][sb], bh[pr][sb + 1]);
                }
        }
    }

    /* warp covers exactly one np (32 px); reduce max/sum/sq across lanes */
    int npf = blockIdx.x * 2 + pxg;
    int b = npf >> 10, np = npf & 1023;
#pragma unroll
    for (int n = 0; n < 4; n++) {
        float v0 = fmaxf(fmaxf(acc[0][n][0], acc[0][n][2]), fmaxf(acc[1][n][0], acc[1][n][2]));
        float v1 = fmaxf(fmaxf(acc[0][n][1], acc[0][n][3]), fmaxf(acc[1][n][1], acc[1][n][3]));
        float s0 = acc[0][n][0] + acc[0][n][2] + acc[1][n][0] + acc[1][n][2];
        float s1 = acc[0][n][1] + acc[0][n][3] + acc[1][n][1] + acc[1][n][3];
        float q0 = acc[0][n][0] * acc[0][n][0] + acc[0][n][2] * acc[0][n][2]
                 + acc[1][n][0] * acc[1][n][0] + acc[1][n][2] * acc[1][n][2];
        float q1 = acc[0][n][1] * acc[0][n][1] + acc[0][n][3] * acc[0][n][3]
                 + acc[1][n][1] * acc[1][n][1] + acc[1][n][3] * acc[1][n][3];
#pragma unroll
        for (int d = 4; d < 32; d <<= 1) {
            v0 = fmaxf(v0, __shfl_xor_sync(0xffffffffu, v0, d));
            v1 = fmaxf(v1, __shfl_xor_sync(0xffffffffu, v1, d));
            s0 += __shfl_xor_sync(0xffffffffu, s0, d);
            s1 += __shfl_xor_sync(0xffffffffu, s1, d);
            q0 += __shfl_xor_sync(0xffffffffu, q0, d);
            q1 += __shfl_xor_sync(0xffffffffu, q1, d);
        }
        if (lane < 4) {
            int co = coB + cog * 32 + n * 8 + (lane << 1);
            out[OUT_XYZ + ((size_t)b * 256 + co) * 1024 + np] = v0;
            out[OUT_XYZ + ((size_t)b * 256 + co + 1) * 1024 + np] = v1;
            atomicAdd(&g_sum[192 + co], s0);
            atomicAdd(&g_sum[192 + co + 1], s1);
            atomicAdd(&g_sq[192 + co], q0);
            atomicAdd(&g_sq[192 + co + 1], q1);
        }
    }
}

__global__ void k_final(float* __restrict__ out) {
    int i = blockIdx.x * 256 + threadIdx.x;
    if (i < NB * 256 * NPQ) {
        int co = (i >> 10) & 255;
        float v = out[OUT_XYZ + i];
        out[OUT_XYZ + i] = fmaxf(fmaf(g_aa[192 + co], v, g_cc[192 + co]), 0.f);
    }
}
__global__ void k_xyz(const float* __restrict__ xyz, const int* __restrict__ smp,
                      float* __restrict__ out) {
    int i = blockIdx.x * 256 + threadIdx.x;
    if (i < NB * NPQ) {
        int b = i >> 10;
        const float* s = xyz + (size_t)(b * NPTS + smp[i]) * 3;
        out[i * 3 + 0] = s[0];
        out[i * 3 + 1] = s[1];
        out[i * 3 + 2] = s[2];
    }
}

extern "C" void kernel_launch(void* const* d_in, const int* in_sizes, int n_in,
                              void* d_out, int out_size) {
    const float* xyz = (const float*)d_in[0];
    const float* pts = (const float*)d_in[1];
    const int*   smp = (const int*)d_in[2];
    const int*   nbr = (const int*)d_in[3];
    const float* W0  = (const float*)d_in[4];
    const float* g0  = (const float*)d_in[6];
    const float* be0 = (const float*)d_in[7];
    const float* W1  = (const float*)d_in[8];
    const float* g1  = (const float*)d_in[10];
    const float* be1 = (const float*)d_in[11];
    const float* W2  = (const float*)d_in[12];
    const float* g2  = (const float*)d_in[14];
    const float* be2 = (const float*)d_in[15];
    float* out = (float*)d_out;

    const int SM0 = 67584;
    const int SM1 = 55296 + 512;
    const int SM2 = 55296 + 1024;
    cudaFuncSetAttribute(k_g0, cudaFuncAttributeMaxDynamicSharedMemorySize, SM0);
    cudaFuncSetAttribute(k_g1, cudaFuncAttributeMaxDynamicSharedMemorySize, SM1);
    cudaFuncSetAttribute(k_g2, cudaFuncAttributeMaxDynamicSharedMemorySize, SM2);

    k_prep<<<128, 256>>>(W0, W1, W2);
    k_g0<<<PXT / 128, 256, SM0>>>(xyz, pts, smp, nbr);
    k_stats0<<<1024, 256>>>();
    k_fold<<<1, 64>>>(g0, be0, 0, 64);
    k_g1<<<PXT / 64, 256, SM1>>>();
    k_stats1<<<2048, 256>>>();
    k_fold<<<1, 128>>>(g1, be1, 64, 128);
    k_g2<<<dim3(PXT / 64, 2), 256, SM2>>>(out);
    k_fold<<<1, 256>>>(g2, be2, 192, 256);
    k_final<<<(NB * 256 * NPQ + 255) / 256, 256>>>(out);
    k_xyz<<<(NB * NPQ + 255) / 256, 256>>>(xyz, smp, out);
}

// round 6
// speedup vs baseline: 3.2214x; 1.2121x over previous
#include <cuda_runtime.h>

#define NPTS  4096
#define NPQ   1024
#define NB    8
#define PXT   262144
#define EPSB  1e-5f
#define OUT_XYZ 24576
#define FLT_BIG 3.4e38f

typedef unsigned int   u32;
typedef unsigned short u16;

/* packed bf16 hi|lo activations, px-major */
__device__ u32 g_y0u[(size_t)PXT * 64];    /* [px][64]  64 MB  */
__device__ u32 g_y1u[(size_t)PXT * 128];   /* [px][128] 128 MB */

/* pre-split pre-transposed points: [b][n][c] packed hi|lo (8 MB) */
__device__ u32 g_pT[(size_t)NB * NPTS * 64];

/* pre-split weights, [co][k] bf16 bits */
__device__ u16 g_W0h[64 * 80],  g_W0l[64 * 80];     /* padded k=80 */
__device__ u16 g_W1h[128 * 64], g_W1l[128 * 64];
__device__ u16 g_W2h[256 * 128], g_W2l[256 * 128];

__device__ float g_sum[448], g_sq[448], g_aa[448], g_cc[448];

/* ---------- helpers ---------- */
__device__ __forceinline__ u32 bf16bits(float v) {
    u32 u = __float_as_uint(v);
    return (u + 0x7fffu + ((u >> 16) & 1u)) >> 16;
}
__device__ __forceinline__ void split2(float v, u32& hb, u32& lb) {
    hb = bf16bits(v);
    lb = bf16bits(v - __uint_as_float(hb << 16));
}
__device__ __forceinline__ u32 packhl(float v) {
    u32 hb, lb; split2(v, hb, lb);
    return (hb << 16) | lb;
}
__device__ __forceinline__ float unpk(u32 p) {
    return __uint_as_float(p & 0xffff0000u) + __uint_as_float((p & 0xffffu) << 16);
}
__device__ __forceinline__ u32 smem_u32_of(const void* p) {
    u32 a;
    asm("{ .reg .u64 t; cvta.to.shared.u64 t, %1; cvt.u32.u64 %0, t; }" : "=r"(a) : "l"(p));
    return a;
}
__device__ __forceinline__ void ldsm4(u32* r, u32 addr) {
    asm volatile("ldmatrix.sync.aligned.m8n8.x4.shared.b16 {%0,%1,%2,%3}, [%4];"
        : "=r"(r[0]), "=r"(r[1]), "=r"(r[2]), "=r"(r[3]) : "r"(addr));
}
__device__ __forceinline__ void hmma(float* d, const u32* a, u32 b0, u32 b1) {
    asm volatile("mma.sync.aligned.m16n8k16.row.col.f32.bf16.bf16.f32 "
        "{%0,%1,%2,%3}, {%4,%5,%6,%7}, {%8,%9}, {%0,%1,%2,%3};"
        : "+f"(d[0]), "+f"(d[1]), "+f"(d[2]), "+f"(d[3])
        : "r"(a[0]), "r"(a[1]), "r"(a[2]), "r"(a[3]), "r"(b0), "r"(b1));
}

extern __shared__ char smc[];

/* ---------- prep: stats zero + weight split images ---------- */
__global__ void k_prep(const float* __restrict__ W0, const float* __restrict__ W1,
                       const float* __restrict__ W2) {
    int t0 = blockIdx.x * blockDim.x + threadIdx.x;
    int nth = gridDim.x * blockDim.x;
    for (int t = t0; t < 448; t += nth) { g_sum[t] = 0.f; g_sq[t] = 0.f; }
    for (int e = t0; e < 64 * 80; e += nth) {
        int co = e / 80, k = e - co * 80;
        float v = (k < 67) ? W0[co * 67 + k] : 0.f;
        u32 hb, lb; split2(v, hb, lb);
        g_W0h[e] = (u16)hb; g_W0l[e] = (u16)lb;
    }
    for (int e = t0; e < 128 * 64; e += nth) {
        u32 hb, lb; split2(W1[e], hb, lb);
        g_W1h[e] = (u16)hb; g_W1l[e] = (u16)lb;
    }
    for (int e = t0; e < 256 * 128; e += nth) {
        u32 hb, lb; split2(W2[e], hb, lb);
        g_W2h[e] = (u16)hb; g_W2l[e] = (u16)lb;
    }
}

/* ---------- transpose+split points: [b][c][n] f32 -> [b][n][c] packed u32 ---------- */
__global__ __launch_bounds__(256) void k_pT(const float* __restrict__ pts) {
    __shared__ u32 t[64][65];
    int b = blockIdx.x >> 6;
    int n0 = (blockIdx.x & 63) * 64;
    int tid = threadIdx.x;
    {
        int n = tid & 63, cq = tid >> 6;
#pragma unroll 4
        for (int i = 0; i < 16; i++) {
            int c = cq * 16 + i;
            t[n][c] = packhl(pts[((size_t)(b * 64 + c)) * NPTS + n0 + n]);
        }
    }
    __syncthreads();
    {
        int c = tid & 63, nq = tid >> 6;
#pragma unroll 4
        for (int i = 0; i < 16; i++) {
            int nn = nq * 16 + i;
            g_pT[((size_t)b * NPTS + n0 + nn) * 64 + c] = t[nn][c];
        }
    }
}

__global__ void k_fold(const float* __restrict__ gamma, const float* __restrict__ beta,
                       int off, int C) {
    int i = blockIdx.x * blockDim.x + threadIdx.x;
    if (i < C) {
        const float inv = 1.0f / (float)PXT;
        float mu = g_sum[off + i] * inv;
        float var = g_sq[off + i] * inv - mu * mu;
        float a = gamma[i] * rsqrtf(var + EPSB);
        g_aa[off + i] = a;
        g_cc[off + i] = beta[i] - a * mu;
    }
}

/* ================= layer 0: gather + GEMM(px128 x co64 x k80) + stats0 ====== */
__global__ __launch_bounds__(256, 2) void k_g0(
    const float* __restrict__ xyz,
    const int* __restrict__ smp, const int* __restrict__ nbr)
{
    const int XHo = 0, XLo = 22528, WHo = 45056, WLo = 56320;
    u16* XH = (u16*)(smc + XHo); u16* XL = (u16*)(smc + XLo);
    u16* WH = (u16*)(smc + WHo); u16* WL = (u16*)(smc + WLo);

    int tid = threadIdx.x, wid = tid >> 5, lane = tid & 31;
    int px0 = blockIdx.x * 128, b = px0 >> 15;

    for (int e = tid; e < 5120; e += 256) {
        int row = e / 80, k = e - row * 80;
        WH[row * 88 + k] = g_W0h[e];
        WL[row * 88 + k] = g_W0l[e];
    }
    {
        int r = tid & 127, half = tid >> 7;
        int px = px0 + r;
        int ni = nbr[px];
        const uint4* src = (const uint4*)&g_pT[((size_t)b * NPTS + ni) * 64];
        if (half == 0) {
            int si = smp[px >> 5];
            const float* xn = xyz + (size_t)(b * NPTS + ni) * 3;
            const float* xc = xyz + (size_t)(b * NPTS + si) * 3;
#pragma unroll
            for (int k = 0; k < 3; k++) {
                u32 hb, lb; split2(xn[k] - xc[k], hb, lb);
                XH[r * 88 + k] = (u16)hb; XL[r * 88 + k] = (u16)lb;
            }
#pragma unroll
            for (int j = 0; j < 8; j++) {
                uint4 w = src[j];
                u32 ww[4] = { w.x, w.y, w.z, w.w };
#pragma unroll
                for (int jj = 0; jj < 4; jj++) {
                    int k = 3 + j * 4 + jj;
                    XH[r * 88 + k] = (u16)(ww[jj] >> 16);
                    XL[r * 88 + k] = (u16)(ww[jj] & 0xffffu);
                }
            }
        } else {
#pragma unroll
            for (int j = 8; j < 16; j++) {
                uint4 w = src[j];
                u32 ww[4] = { w.x, w.y, w.z, w.w };
#pragma unroll
                for (int jj = 0; jj < 4; jj++) {
                    int k = 3 + j * 4 + jj;
                    XH[r * 88 + k] = (u16)(ww[jj] >> 16);
                    XL[r * 88 + k] = (u16)(ww[jj] & 0xffffu);
                }
            }
#pragma unroll
            for (int k = 67; k < 80; k++) { XH[r * 88 + k] = 0; XL[r * 88 + k] = 0; }
        }
    }
    __syncthreads();

    int pxg = wid >> 1, cog = wid & 1;
    u32 smb = smem_u32_of(smc);
    u32 arow = (u32)(pxg * 32 + (lane & 15)) * 176 + ((lane >> 4) << 4);
    u32 brow = (u32)(cog * 32 + ((lane >> 4) << 3) + (lane & 7)) * 176 + (((lane >> 3) & 1) << 4);

    float acc[2][4][4];
#pragma unroll
    for (int m = 0; m < 2; m++)
#pragma unroll
        for (int n = 0; n < 4; n++)
#pragma unroll
            for (int i = 0; i < 4; i++) acc[m][n][i] = 0.f;

#pragma unroll
    for (int ks = 0; ks < 5; ks++) {
        u32 ah[2][4], al[2][4], bh[2][4], bl[2][4];
#pragma unroll
        for (int m = 0; m < 2; m++) {
            ldsm4(ah[m], smb + XHo + arow + (u32)m * 16 * 176 + ks * 32);
            ldsm4(al[m], smb + XLo + arow + (u32)m * 16 * 176 + ks * 32);
        }
#pragma unroll
        for (int g = 0; g < 2; g++) {
            ldsm4(bh[g], smb + WHo + brow + (u32)g * 16 * 176 + ks * 32);
            ldsm4(bl[g], smb + WLo + brow + (u32)g * 16 * 176 + ks * 32);
        }
#pragma unroll
        for (int m = 0; m < 2; m++)
#pragma unroll
            for (int n = 0; n < 4; n++) {
                int pr = n >> 1, sb = (n & 1) * 2;
                hmma(acc[m][n], ah[m], bh[pr][sb], bh[pr][sb + 1]);
                hmma(acc[m][n], ah[m], bl[pr][sb], bl[pr][sb + 1]);
                hmma(acc[m][n], al[m], bh[pr][sb], bh[pr][sb + 1]);
            }
    }

#pragma unroll
    for (int n = 0; n < 4; n++) {
        float s0 = 0.f, q0 = 0.f, s1 = 0.f, q1 = 0.f;
#pragma unroll
        for (int m = 0; m < 2; m++) {
            int px = px0 + pxg * 32 + m * 16 + (lane >> 2);
            int co = cog * 32 + n * 8 + ((lane & 3) << 1);
            uint2 v0 = { packhl(acc[m][n][0]), packhl(acc[m][n][1]) };
            uint2 v1 = { packhl(acc[m][n][2]), packhl(acc[m][n][3]) };
            *(uint2*)&g_y0u[(size_t)px * 64 + co] = v0;
            *(uint2*)&g_y0u[(size_t)(px + 8) * 64 + co] = v1;
            float a0 = acc[m][n][0], a1 = acc[m][n][1], a2 = acc[m][n][2], a3 = acc[m][n][3];
            s0 += a0 + a2; q0 += a0 * a0 + a2 * a2;
            s1 += a1 + a3; q1 += a1 * a1 + a3 * a3;
        }
#pragma unroll
        for (int d = 4; d < 32; d <<= 1) {
            s0 += __shfl_xor_sync(0xffffffffu, s0, d);
            q0 += __shfl_xor_sync(0xffffffffu, q0, d);
            s1 += __shfl_xor_sync(0xffffffffu, s1, d);
            q1 += __shfl_xor_sync(0xffffffffu, q1, d);
        }
        if (lane < 4) {
            int co = cog * 32 + n * 8 + (lane << 1);
            atomicAdd(&g_sum[co], s0);
            atomicAdd(&g_sum[co + 1], s1);
            atomicAdd(&g_sq[co], q0);
            atomicAdd(&g_sq[co + 1], q1);
        }
    }
}

/* ========== layer 1: inline fold0, GEMM(px128 x co128 x k64) + stats1 ======= */
__global__ __launch_bounds__(256, 2) void k_g1(const float* __restrict__ gamma,
                                               const float* __restrict__ beta)
{
    const int XHo = 0, XLo = 18432, WHo = 36864, WLo = 55296;
    u16* WH = (u16*)(smc + WHo); u16* WL = (u16*)(smc + WLo);
    float* s_a = (float*)(smc + 73728);
    float* s_c = s_a + 64;

    int tid = threadIdx.x, wid = tid >> 5, lane = tid & 31;
    int px0 = blockIdx.x * 128;

    if (tid < 64) {
        const float inv = 1.0f / (float)PXT;
        float mu = g_sum[tid] * inv;
        float var = g_sq[tid] * inv - mu * mu;
        float a = gamma[tid] * rsqrtf(var + EPSB);
        s_a[tid] = a;
        s_c[tid] = beta[tid] - a * mu;
    }
    for (int e = tid; e < 4096; e += 256) {         /* W1 as u32 pairs */
        int row = e >> 5, kp = e & 31;
        ((u32*)(WH + row * 72))[kp] = ((const u32*)g_W1h)[row * 32 + kp];
        ((u32*)(WL + row * 72))[kp] = ((const u32*)g_W1l)[row * 32 + kp];
    }
    __syncthreads();
    {
        int r = tid >> 1, half = tid & 1;
        int px = px0 + r;
        const uint4* src = (const uint4*)&g_y0u[(size_t)px * 64 + half * 32];
        u32* xh = (u32*)(smc + XHo + r * 144 + half * 64);
        u32* xl = (u32*)(smc + XLo + r * 144 + half * 64);
#pragma unroll
        for (int j = 0; j < 8; j++) {
            uint4 w = src[j];
            u32 ww[4] = { w.x, w.y, w.z, w.w };
            u32 h2[2] = { 0, 0 }, l2[2] = { 0, 0 };
#pragma unroll
            for (int jj = 0; jj < 4; jj++) {
                int k = half * 32 + j * 4 + jj;
                float v = fmaxf(fmaf(s_a[k], unpk(ww[jj]), s_c[k]), 0.f);
                u32 hb, lb; split2(v, hb, lb);
                h2[jj >> 1] |= hb << ((jj & 1) * 16);
                l2[jj >> 1] |= lb << ((jj & 1) * 16);
            }
            xh[j * 2] = h2[0]; xh[j * 2 + 1] = h2[1];
            xl[j * 2] = l2[0]; xl[j * 2 + 1] = l2[1];
        }
    }
    __syncthreads();

    int pxg = wid >> 1, cog = wid & 1;
    u32 smb = smem_u32_of(smc);
    u32 arow = (u32)(pxg * 32 + (lane & 15)) * 144 + ((lane >> 4) << 4);
    u32 brow = (u32)(cog * 64 + ((lane >> 4) << 3) + (lane & 7)) * 144 + (((lane >> 3) & 1) << 4);

    float acc[2][8][4];
#pragma unroll
    for (int m = 0; m < 2; m++)
#pragma unroll
        for (int n = 0; n < 8; n++)
#pragma unroll
            for (int i = 0; i < 4; i++) acc[m][n][i] = 0.f;

#pragma unroll
    for (int ks = 0; ks < 4; ks++) {
        u32 ah[2][4], al[2][4];
#pragma unroll
        for (int m = 0; m < 2; m++) {
            ldsm4(ah[m], smb + XHo + arow + (u32)m * 16 * 144 + ks * 32);
            ldsm4(al[m], smb + XLo + arow + (u32)m * 16 * 144 + ks * 32);
        }
#pragma unroll
        for (int g = 0; g < 4; g++) {
            u32 bh[4], bl[4];
            ldsm4(bh, smb + WHo + brow + (u32)g * 16 * 144 + ks * 32);
            ldsm4(bl, smb + WLo + brow + (u32)g * 16 * 144 + ks * 32);
#pragma unroll
            for (int t = 0; t < 2; t++) {
                int n = g * 2 + t, sb = t * 2;
#pragma unroll
                for (int m = 0; m < 2; m++) {
                    hmma(acc[m][n], ah[m], bh[sb], bh[sb + 1]);
                    hmma(acc[m][n], ah[m], bl[sb], bl[sb + 1]);
                    hmma(acc[m][n], al[m], bh[sb], bh[sb + 1]);
                }
            }
        }
    }

#pragma unroll
    for (int n = 0; n < 8; n++) {
        float s0 = 0.f, q0 = 0.f, s1 = 0.f, q1 = 0.f;
#pragma unroll
        for (int m = 0; m < 2; m++) {
            int px = px0 + pxg * 32 + m * 16 + (lane >> 2);
            int co = cog * 64 + n * 8 + ((lane & 3) << 1);
            uint2 v0 = { packhl(acc[m][n][0]), packhl(acc[m][n][1]) };
            uint2 v1 = { packhl(acc[m][n][2]), packhl(acc[m][n][3]) };
            *(uint2*)&g_y1u[(size_t)px * 128 + co] = v0;
            *(uint2*)&g_y1u[(size_t)(px + 8) * 128 + co] = v1;
            float a0 = acc[m][n][0], a1 = acc[m][n][1], a2 = acc[m][n][2], a3 = acc[m][n][3];
            s0 += a0 + a2; q0 += a0 * a0 + a2 * a2;
            s1 += a1 + a3; q1 += a1 * a1 + a3 * a3;
        }
#pragma unroll
        for (int d = 4; d < 32; d <<= 1) {
            s0 += __shfl_xor_sync(0xffffffffu, s0, d);
            q0 += __shfl_xor_sync(0xffffffffu, q0, d);
            s1 += __shfl_xor_sync(0xffffffffu, s1, d);
            q1 += __shfl_xor_sync(0xffffffffu, q1, d);
        }
        if (lane < 4) {
            int co = cog * 64 + n * 8 + (lane << 1);
            atomicAdd(&g_sum[64 + co], s0);
            atomicAdd(&g_sum[64 + co + 1], s1);
            atomicAdd(&g_sq[64 + co], q0);
            atomicAdd(&g_sq[64 + co + 1], q1);
        }
    }
}

/* == layer 2: inline fold1, X staged once, GEMM(px128 x co256 x k128) + stats2 + NS-max == */
__global__ __launch_bounds__(256, 2) void k_g2(const float* __restrict__ gamma,
                                               const float* __restrict__ beta,
                                               float* __restrict__ out)
{
    const int XHo = 0, XLo = 34816, WHo = 69632, WLo = 88064;
    u16* WH = (u16*)(smc + WHo); u16* WL = (u16*)(smc + WLo);
    float* s_a = (float*)(smc + 106496);
    float* s_c = s_a + 128;

    int tid = threadIdx.x, wid = tid >> 5, lane = tid & 31;
    int px0 = blockIdx.x * 128;

    if (tid < 128) {
        const float inv = 1.0f / (float)PXT;
        float mu = g_sum[64 + tid] * inv;
        float var = g_sq[64 + tid] * inv - mu * mu;
        float a = gamma[tid] * rsqrtf(var + EPSB);
        s_a[tid] = a;
        s_c[tid] = beta[tid] - a * mu;
    }
    __syncthreads();
    {
        int r = tid >> 1, half = tid & 1;
        int px = px0 + r;
        const uint4* src = (const uint4*)&g_y1u[(size_t)px * 128 + half * 64];
        u32* xh = (u32*)(smc + XHo + r * 272 + half * 128);
        u32* xl = (u32*)(smc + XLo + r * 272 + half * 128);
#pragma unroll
        for (int j = 0; j < 16; j++) {
            uint4 w = src[j];
            u32 ww[4] = { w.x, w.y, w.z, w.w };
            u32 h2[2] = { 0, 0 }, l2[2] = { 0, 0 };
#pragma unroll
            for (int jj = 0; jj < 4; jj++) {
                int k = half * 64 + j * 4 + jj;
                float v = fmaxf(fmaf(s_a[k], unpk(ww[jj]), s_c[k]), 0.f);
                u32 hb, lb; split2(v, hb, lb);
                h2[jj >> 1] |= hb << ((jj & 1) * 16);
                l2[jj >> 1] |= lb << ((jj & 1) * 16);
            }
            xh[j * 2] = h2[0]; xh[j * 2 + 1] = h2[1];
            xl[j * 2] = l2[0]; xl[j * 2 + 1] = l2[1];
        }
    }

    int pxg = wid >> 1, cog = wid & 1;
    u32 smb = smem_u32_of(smc);
    u32 arow = (u32)(pxg * 32 + (lane & 15)) * 272 + ((lane >> 4) << 4);
    u32 brow = (u32)(cog * 64 + ((lane >> 4) << 3) + (lane & 7)) * 144 + (((lane >> 3) & 1) << 4);

    int np = blockIdx.x * 4 + pxg;
    int b = np >> 10, npq = np & 1023;

    for (int h = 0; h < 2; h++) {
        float acc[2][8][4];
#pragma unroll
        for (int m = 0; m < 2; m++)
#pragma unroll
            for (int n = 0; n < 8; n++)
#pragma unroll
                for (int i = 0; i < 4; i++) acc[m][n][i] = 0.f;

        for (int kc = 0; kc < 2; kc++) {
            __syncthreads();   /* prior W reads done (and X staged, first iter) */
            for (int e = tid; e < 4096; e += 256) {
                int row = e >> 5, kp = e & 31;
                ((u32*)(WH + row * 72))[kp] =
                    ((const u32*)g_W2h)[(size_t)(h * 128 + row) * 64 + kc * 32 + kp];
                ((u32*)(WL + row * 72))[kp] =
                    ((const u32*)g_W2l)[(size_t)(h * 128 + row) * 64 + kc * 32 + kp];
            }
            __syncthreads();
#pragma unroll
            for (int ks = 0; ks < 4; ks++) {
                int kk = kc * 4 + ks;
                u32 ah[2][4], al[2][4];
#pragma unroll
                for (int m = 0; m < 2; m++) {
                    ldsm4(ah[m], smb + XHo + arow + (u32)m * 16 * 272 + kk * 32);
                    ldsm4(al[m], smb + XLo + arow + (u32)m * 16 * 272 + kk * 32);
                }
#pragma unroll
                for (int g = 0; g < 4; g++) {
                    u32 bh[4], bl[4];
                    ldsm4(bh, smb + WHo + brow + (u32)g * 16 * 144 + ks * 32);
                    ldsm4(bl, smb + WLo + brow + (u32)g * 16 * 144 + ks * 32);
#pragma unroll
                    for (int t = 0; t < 2; t++) {
                        int n = g * 2 + t, sb = t * 2;
#pragma unroll
                        for (int m = 0; m < 2; m++) {
                            hmma(acc[m][n], ah[m], bh[sb], bh[sb + 1]);
                            hmma(acc[m][n], ah[m], bl[sb], bl[sb + 1]);
                            hmma(acc[m][n], al[m], bh[sb], bh[sb + 1]);
                        }
                    }
                }
            }
        }

#pragma unroll
        for (int n = 0; n < 8; n++) {
            float v0 = -FLT_BIG, v1 = -FLT_BIG;
            float s0 = 0.f, q0 = 0.f, s1 = 0.f, q1 = 0.f;
#pragma unroll
            for (int m = 0; m < 2; m++) {
                float a0 = acc[m][n][0], a1 = acc[m][n][1], a2 = acc[m][n][2], a3 = acc[m][n][3];
                v0 = fmaxf(v0, fmaxf(a0, a2));
                v1 = fmaxf(v1, fmaxf(a1, a3));
                s0 += a0 + a2; q0 += a0 * a0 + a2 * a2;
                s1 += a1 + a3; q1 += a1 * a1 + a3 * a3;
            }
#pragma unroll
            for (int d = 4; d < 32; d <<= 1) {
                v0 = fmaxf(v0, __shfl_xor_sync(0xffffffffu, v0, d));
                v1 = fmaxf(v1, __shfl_xor_sync(0xffffffffu, v1, d));
                s0 += __shfl_xor_sync(0xffffffffu, s0, d);
                q0 += __shfl_xor_sync(0xffffffffu, q0, d);
                s1 += __shfl_xor_sync(0xffffffffu, s1, d);
                q1 += __shfl_xor_sync(0xffffffffu, q1, d);
            }
            if (lane < 4) {
                int co = h * 128 + cog * 64 + n * 8 + (lane << 1);
                out[OUT_XYZ + ((size_t)b * 256 + co) * 1024 + npq] = v0;
                out[OUT_XYZ + ((size_t)b * 256 + co + 1) * 1024 + npq] = v1;
                atomicAdd(&g_sum[192 + co], s0);
                atomicAdd(&g_sum[192 + co + 1], s1);
                atomicAdd(&g_sq[192 + co], q0);
                atomicAdd(&g_sq[192 + co + 1], q1);
            }
        }
    }
}

/* BN2+ReLU in place + xyz gather, one kernel */
__global__ void k_fx(const float* __restrict__ xyz, const int* __restrict__ smp,
                     float* __restrict__ out) {
    int i = blockIdx.x * 256 + threadIdx.x;
    const int total = NB * 256 * NPQ;
    if (i < total) {
        int co = (i >> 10) & 255;
        float v = out[OUT_XYZ + i];
        out[OUT_XYZ + i] = fmaxf(fmaf(g_aa[192 + co], v, g_cc[192 + co]), 0.f);
    } else {
        int j = i - total;
        if (j < NB * NPQ) {
            int b = j >> 10;
            const float* s = xyz + (size_t)(b * NPTS + smp[j]) * 3;
            out[j * 3 + 0] = s[0];
            out[j * 3 + 1] = s[1];
            out[j * 3 + 2] = s[2];
        }
    }
}

extern "C" void kernel_launch(void* const* d_in, const int* in_sizes, int n_in,
                              void* d_out, int out_size) {
    const float* xyz = (const float*)d_in[0];
    const float* pts = (const float*)d_in[1];
    const int*   smp = (const int*)d_in[2];
    const int*   nbr = (const int*)d_in[3];
    const float* W0  = (const float*)d_in[4];
    const float* g0  = (const float*)d_in[6];
    const float* be0 = (const float*)d_in[7];
    const float* W1  = (const float*)d_in[8];
    const float* g1  = (const float*)d_in[10];
    const float* be1 = (const float*)d_in[11];
    const float* W2  = (const float*)d_in[12];
    const float* g2  = (const float*)d_in[14];
    const float* be2 = (const float*)d_in[15];
    float* out = (float*)d_out;

    const int SM0 = 67584;
    const int SM1 = 74240;
    const int SM2 = 107520;
    cudaFuncSetAttribute(k_g0, cudaFuncAttributeMaxDynamicSharedMemorySize, SM0);
    cudaFuncSetAttribute(k_g1, cudaFuncAttributeMaxDynamicSharedMemorySize, SM1);
    cudaFuncSetAttribute(k_g2, cudaFuncAttributeMaxDynamicSharedMemorySize, SM2);

    k_prep<<<128, 256>>>(W0, W1, W2);
    k_pT<<<512, 256>>>(pts);
    k_g0<<<PXT / 128, 256, SM0>>>(xyz, smp, nbr);
    k_g1<<<PXT / 128, 256, SM1>>>(g0, be0);
    k_g2<<<PXT / 128, 256, SM2>>>(g1, be1, out);
    k_fold<<<1, 256>>>(g2, be2, 192, 256);
    k_fx<<<(NB * 256 * NPQ + NB * NPQ) / 256, 256>>>(xyz, smp, out);
}